// round 11
// baseline (speedup 1.0000x reference)
#include <cuda_runtime.h>

#define F_FIELDS 17
#define HH 300
#define WW 400
#define H_F 38
#define W_F 50
#define NPTS (F_FIELDS * H_F * W_F)          // 32300
#define OUT_ELEMS (F_FIELDS * HH * WW)       // 2,040,000
#define N4 (OUT_ELEMS / 4)                   // 510,000
#define SLOTS 4

// Scratch accumulator + barrier state. Zero-initialized at module load.
// Invariants restored every run (scratch re-zeroed, count self-resets,
// epoch is monotonic) -> deterministic across graph replays.
__device__ float g_scratch[OUT_ELEMS];
__device__ unsigned g_count;
__device__ volatile unsigned g_epoch;

__global__ void __launch_bounds__(256, 4) cifhr_fused(
    const float*  __restrict__ x,       // (17, 5, 38, 50)
    const float4* __restrict__ cifhr,   // (17, 300, 400) as float4
    float4*       __restrict__ out
) {
    const int warp = threadIdx.x >> 5;
    const int lane = threadIdx.x & 31;
    const int nwarps = gridDim.x * 8;
    const int gtid = blockIdx.x * 256 + threadIdx.x;
    const int T = gridDim.x * 256;

    // ---------------- Phase 1: scatter (REDG.128 splats) ----------------
    for (int p = blockIdx.x * 8 + warp; p < NPTS; p += nwarps) {
        const int f = p / (H_F * W_F);
        const int hw = p - f * (H_F * W_F);
        const float* base = x + (size_t)f * 5 * (H_F * W_F) + hw;

        const float v = base[0];
        if (!(v >= 0.1f)) continue;                     // v >= V_TH (warp-uniform)
        const float scale = base[4 * H_F * W_F];
        if (!(scale * 8.0f >= 0.0f)) continue;          // MIN_SCALE = 0

        const float px = base[1 * H_F * W_F] * 8.0f;
        const float py = base[2 * H_F * W_F] * 8.0f;

        const float sigma  = fmaxf(1.0f, 4.0f * scale);
        const float sigma2 = sigma * sigma;
        const float trunc2 = 4.0f * sigma2;
        const float k8     = (-0.5f / sigma2) * 0.125f; // ninv/8
        const float value  = v * 0.0625f;               // v/16

        const int cx = (int)rintf(px);                  // round-half-even
        const int cy = (int)rintf(py);
        int rb = (int)floorf(2.0f * sigma + 0.5f);      // exact disc bound
        if (rb > 13) rb = 13;

        const int y0 = max(cy - rb, 0), y1 = min(cy + rb, HH - 1);
        const int x0 = max(cx - rb, 0), x1 = min(cx + rb, WW - 1);
        if (y0 > y1 || x0 > x1) continue;

        const int xs = x0 & ~3;
        const int Wg = (((x1 | 3) + 1) - xs) >> 2;
        const int Ng = (y1 - y0 + 1) * Wg;

        int row = lane / Wg;
        int gx  = lane - row * Wg;
        const int drow = 32 / Wg;
        const int dgx  = 32 - drow * Wg;

        float* __restrict__ fout = g_scratch + (size_t)f * HH * WW;

        for (int g = lane; g < Ng; g += 32, row += drow, gx += dgx) {
            if (gx >= Wg) { gx -= Wg; row += 1; }
            const int yy = y0 + row;
            const int xb = xs + (gx << 2);

            const float fdy = (float)yy - py;
            const float dy2 = fdy * fdy;
            const float rem = trunc2 - dy2;
            if (rem < 0.0f) continue;
            const bool ny = dy2 < 0.25f;

            float c[4];
            bool any = false;
            #pragma unroll
            for (int j = 0; j < 4; j++) {
                const int xx = xb + j;
                const float fdx = (float)xx - px;
                const float dx2 = fdx * fdx;
                const float d2 = dy2 + dx2;
                float t = fmaf(d2, k8, 1.0f);           // (1 + t/8)^8
                t = t * t; t = t * t; t = t * t;
                const float gg = (ny && dx2 < 0.25f) ? 1.0f : t;
                const bool in = (xx >= x0) & (xx <= x1) & (dx2 <= rem);
                c[j] = in ? value * gg : 0.0f;
                any |= in;
            }
            if (any) {
                float* addr = fout + yy * WW + xb;
                asm volatile("red.global.add.v4.f32 [%0], {%1,%2,%3,%4};"
                             :: "l"(addr), "f"(c[0]), "f"(c[1]), "f"(c[2]), "f"(c[3])
                             : "memory");
            }
        }
    }

    // ------ Prefetch cifhr (independent of scatter; overlaps stragglers) ------
    float4 cpre[SLOTS];
    #pragma unroll
    for (int s = 0; s < SLOTS; s++) {
        const int i = gtid + s * T;
        if (i < N4) cpre[s] = cifhr[i];
    }

    // ---------------- Device-wide barrier (sense via epoch) ----------------
    const unsigned e0 = g_epoch;        // read BEFORE arriving: epoch can't pass us
    __syncthreads();                    // whole block done with phase 1
    if (threadIdx.x == 0) {
        __threadfence();                // REDs visible before arrive
        const unsigned old = atomicAdd(&g_count, 1u);
        if (old == gridDim.x - 1) {
            g_count = 0;                // sole writer here; reset for next replay
            __threadfence();
            g_epoch = e0 + 1;           // release
        } else {
            while (g_epoch == e0) { __nanosleep(100); }
        }
        __threadfence();                // acquire
    }
    __syncthreads();

    // ---------------- Phase 2: finish (scratch is complete) ----------------
    float4* __restrict__ sc = reinterpret_cast<float4*>(g_scratch);
    const float4 z = make_float4(0.0f, 0.0f, 0.0f, 0.0f);
    #pragma unroll
    for (int s = 0; s < SLOTS; s++) {
        const int i = gtid + s * T;
        if (i < N4) {
            const float4 sv = sc[i];
            float4 o;
            o.x = fminf(cpre[s].x + sv.x, 1.0f);
            o.y = fminf(cpre[s].y + sv.y, 1.0f);
            o.z = fminf(cpre[s].z + sv.z, 1.0f);
            o.w = fminf(cpre[s].w + sv.w, 1.0f);
            out[i] = o;
            sc[i] = z;
        }
    }
    // Safety tail if grid*256*SLOTS < N4 (tiny or absent on GB300)
    for (int i = gtid + SLOTS * T; i < N4; i += T) {
        const float4 sv = sc[i];
        const float4 c = cifhr[i];
        float4 o;
        o.x = fminf(c.x + sv.x, 1.0f);
        o.y = fminf(c.y + sv.y, 1.0f);
        o.z = fminf(c.z + sv.z, 1.0f);
        o.w = fminf(c.w + sv.w, 1.0f);
        out[i] = o;
        sc[i] = z;
    }
}

extern "C" void kernel_launch(void* const* d_in, const int* in_sizes, int n_in,
                              void* d_out, int out_size) {
    const float* cifhr = (const float*)d_in[0];
    const float* x     = (const float*)d_in[1];
    float* out = (float*)d_out;

    int sms = 148;
    cudaDeviceGetAttribute(&sms, cudaDevAttrMultiProcessorCount, 0);
    // __launch_bounds__(256, 4) guarantees >= 4 resident blocks/SM, so a grid
    // of sms*4 is fully co-resident -> the in-kernel barrier cannot deadlock.
    const int grid = sms * 4;

    cifhr_fused<<<grid, 256>>>(x, (const float4*)cifhr, (float4*)out);
}

// round 13
// speedup vs baseline: 1.1861x; 1.1861x over previous
#include <cuda_runtime.h>

#define F_FIELDS 17
#define HH 300
#define WW 400
#define H_F 38
#define W_F 50
#define NPTS (F_FIELDS * H_F * W_F)          // 32300
#define OUT_ELEMS (F_FIELDS * HH * WW)       // 2,040,000
#define N4 (OUT_ELEMS / 4)                   // 510,000

// Static scratch accumulator. Zero-initialized at module load; the epilogue
// re-zeroes it every run, so the "zero at entry" invariant holds for the
// correctness run and for every graph replay.
__device__ float g_scratch[OUT_ELEMS];

// One warp per point: splat the truncated-Gaussian disc into g_scratch with
// aligned red.global.add.v4.f32 (no return value -> REDG.128).
__global__ void __launch_bounds__(256) cifhr_scatter_v4(
    const float* __restrict__ x    // (17, 5, 38, 50)
) {
    // PDL: allow dependent (finish) blocks to launch into freed SM slots as
    // this grid drains. No-op if the dependent wasn't launched with the attr.
    asm volatile("griddepcontrol.launch_dependents;");

    const int warp = threadIdx.x >> 5;
    const int lane = threadIdx.x & 31;
    const int p = blockIdx.x * 8 + warp;
    if (p >= NPTS) return;

    const int f = p / (H_F * W_F);
    const int hw = p - f * (H_F * W_F);
    const float* base = x + (size_t)f * 5 * (H_F * W_F) + hw;

    const float v = base[0];
    if (!(v >= 0.1f)) return;                       // v >= V_TH
    const float scale = base[4 * H_F * W_F];
    if (!(scale * 8.0f >= 0.0f)) return;            // MIN_SCALE = 0

    const float px = base[1 * H_F * W_F] * 8.0f;
    const float py = base[2 * H_F * W_F] * 8.0f;

    const float sigma  = fmaxf(1.0f, 4.0f * scale); // max(1, 0.5*scale*8)
    const float sigma2 = sigma * sigma;
    const float trunc2 = 4.0f * sigma2;
    const float k8     = (-0.5f / sigma2) * 0.125f; // ninv/8
    const float value  = v * 0.0625f;               // v/16

    const int cx = (int)rintf(px);                  // round-half-even == jnp.round
    const int cy = (int)rintf(py);

    // |dy| > 2*sigma + 0.5  =>  (yy-py)^2 > 4*sigma^2 : provably fails mask
    int rb = (int)floorf(2.0f * sigma + 0.5f);
    if (rb > 13) rb = 13;

    const int y0 = max(cy - rb, 0), y1 = min(cy + rb, HH - 1);
    const int x0 = max(cx - rb, 0), x1 = min(cx + rb, WW - 1);
    if (y0 > y1 || x0 > x1) return;

    const int xs = x0 & ~3;                         // aligned start, >= 0
    const int Wg = (((x1 | 3) + 1) - xs) >> 2;      // groups/row; end <= 400
    const int Ng = (y1 - y0 + 1) * Wg;

    int row = lane / Wg;
    int gx  = lane - row * Wg;
    const int drow = 32 / Wg;
    const int dgx  = 32 - drow * Wg;

    float* __restrict__ fout = g_scratch + (size_t)f * HH * WW;

    for (int g = lane; g < Ng; g += 32, row += drow, gx += dgx) {
        if (gx >= Wg) { gx -= Wg; row += 1; }
        const int yy = y0 + row;
        const int xb = xs + (gx << 2);

        const float fdy = (float)yy - py;
        const float dy2 = fdy * fdy;
        const float rem = trunc2 - dy2;             // row-extent reject
        if (rem < 0.0f) continue;
        const bool ny = dy2 < 0.25f;

        float c[4];
        bool any = false;
        #pragma unroll
        for (int j = 0; j < 4; j++) {
            const int xx = xb + j;
            const float fdx = (float)xx - px;
            const float dx2 = fdx * fdx;
            const float d2 = dy2 + dx2;
            float t = fmaf(d2, k8, 1.0f);           // (1 + t/8)^8
            t = t * t; t = t * t; t = t * t;
            const float gg = (ny && dx2 < 0.25f) ? 1.0f : t;
            const bool in = (xx >= x0) & (xx <= x1) & (dx2 <= rem);
            c[j] = in ? value * gg : 0.0f;
            any |= in;
        }

        if (any) {
            float* addr = fout + yy * WW + xb;      // 16B aligned, in-row
            asm volatile("red.global.add.v4.f32 [%0], {%1,%2,%3,%4};"
                         :: "l"(addr), "f"(c[0]), "f"(c[1]), "f"(c[2]), "f"(c[3])
                         : "memory");
        }
    }
}

// Fused epilogue with PDL overlap: load cifhr BEFORE griddepcontrol.wait so
// its DRAM latency + block ramp overlap the scatter's drain. After the wait
// (primary grid complete, its memory visible), combine with scratch, clamp,
// store, and re-zero scratch for the next graph replay.
__global__ void __launch_bounds__(256) cifhr_finish(
    const float4* __restrict__ cifhr, float4* __restrict__ out
) {
    const int i = blockIdx.x * blockDim.x + threadIdx.x;
    float4 c = make_float4(0.f, 0.f, 0.f, 0.f);
    if (i < N4) c = cifhr[i];                       // pre-sync prefetch

    asm volatile("griddepcontrol.wait;" ::: "memory");

    if (i >= N4) return;
    float4* __restrict__ sc = reinterpret_cast<float4*>(g_scratch);
    const float4 s = sc[i];
    float4 o;
    o.x = fminf(c.x + s.x, 1.0f);
    o.y = fminf(c.y + s.y, 1.0f);
    o.z = fminf(c.z + s.z, 1.0f);
    o.w = fminf(c.w + s.w, 1.0f);
    out[i] = o;
    sc[i] = make_float4(0.0f, 0.0f, 0.0f, 0.0f);
}

extern "C" void kernel_launch(void* const* d_in, const int* in_sizes, int n_in,
                              void* d_out, int out_size) {
    const float* cifhr = (const float*)d_in[0];
    const float* x     = (const float*)d_in[1];
    float* out = (float*)d_out;

    const int blocks = (NPTS + 7) / 8;              // 8 warps/block, 1 pt/warp
    cifhr_scatter_v4<<<blocks, 256>>>(x);

    // Finish with programmatic dependent launch (overlaps scatter drain).
    cudaLaunchConfig_t cfg = {};
    cfg.gridDim  = dim3((N4 + 255) / 256, 1, 1);
    cfg.blockDim = dim3(256, 1, 1);
    cfg.dynamicSmemBytes = 0;
    cfg.stream = 0;
    cudaLaunchAttribute attr[1];
    attr[0].id = cudaLaunchAttributeProgrammaticStreamSerialization;
    attr[0].val.programmaticStreamSerializationAllowed = 1;
    cfg.attrs = attr;
    cfg.numAttrs = 1;
    (void)cudaLaunchKernelEx(&cfg, cifhr_finish,
                             (const float4*)cifhr, (float4*)out);
}